// round 15
// baseline (speedup 1.0000x reference)
#include <cuda_runtime.h>
#include <cuda_bf16.h>
#include <cstdint>

#define SEQ 8192
#define EMB 768
#define DIM 64
#define BM 128
#define BN 64
#define NSPLIT 2
#define KVPER (SEQ / NSPLIT)
#define NT (KVPER / BN)
#define L2E 1.4426950408889634f
#define ROWB 144   // padded smem row bytes (64 bf16 = 128B data + 16B pad)

__device__ __nv_bfloat16 g_Qh[SEQ * DIM], g_Ql[SEQ * DIM];
__device__ __nv_bfloat16 g_Kh[SEQ * DIM], g_Kl[SEQ * DIM];
__device__ __nv_bfloat16 g_Vh[SEQ * DIM], g_Vl[SEQ * DIM];
__device__ float g_Op[NSPLIT * SEQ * DIM];
__device__ float g_m[NSPLIT * SEQ], g_l[NSPLIT * SEQ];

__device__ __forceinline__ uint32_t smem_u32(const void* p) {
    uint32_t a;
    asm("{ .reg .u64 t; cvta.to.shared.u64 t, %1; cvt.u32.u64 %0, t; }" : "=r"(a) : "l"(p));
    return a;
}
__device__ __forceinline__ float ex2f(float x) {
    float y; asm("ex2.approx.ftz.f32 %0, %1;" : "=f"(y) : "f"(x)); return y;
}
__device__ __forceinline__ void cpa16(uint32_t dst, const void* src) {
    asm volatile("cp.async.cg.shared.global [%0], [%1], 16;" :: "r"(dst), "l"(src));
}
#define CP_COMMIT() asm volatile("cp.async.commit_group;" ::: "memory")
#define CP_WAIT0()  asm volatile("cp.async.wait_group 0;" ::: "memory")
#define CP_WAIT1()  asm volatile("cp.async.wait_group 1;" ::: "memory")

__device__ __forceinline__ uint32_t packbf(float lo, float hi) {
    uint32_t r; asm("cvt.rn.bf16x2.f32 %0, %1, %2;" : "=r"(r) : "f"(hi), "f"(lo)); return r;
}
__device__ __forceinline__ uint32_t totf(float x) {
    uint32_t r; asm("cvt.rna.tf32.f32 %0, %1;" : "=r"(r) : "f"(x)); return r;
}

#define LDSM4(r, a) asm volatile( \
    "ldmatrix.sync.aligned.m8n8.x4.shared.b16 {%0,%1,%2,%3}, [%4];" \
    : "=r"((r)[0]), "=r"((r)[1]), "=r"((r)[2]), "=r"((r)[3]) : "r"(a))
#define LDSM4T(r, a) asm volatile( \
    "ldmatrix.sync.aligned.m8n8.x4.trans.shared.b16 {%0,%1,%2,%3}, [%4];" \
    : "=r"((r)[0]), "=r"((r)[1]), "=r"((r)[2]), "=r"((r)[3]) : "r"(a))
#define MMA(d, a, b0, b1) asm volatile( \
    "mma.sync.aligned.m16n8k16.row.col.f32.bf16.bf16.f32 " \
    "{%0,%1,%2,%3}, {%4,%5,%6,%7}, {%8,%9}, {%0,%1,%2,%3};" \
    : "+f"((d)[0]), "+f"((d)[1]), "+f"((d)[2]), "+f"((d)[3]) \
    : "r"((a)[0]), "r"((a)[1]), "r"((a)[2]), "r"((a)[3]), "r"(b0), "r"(b1))
#define MMAT(d, a, b0, b1) asm volatile( \
    "mma.sync.aligned.m16n8k8.row.col.f32.tf32.tf32.f32 " \
    "{%0,%1,%2,%3}, {%4,%5,%6,%7}, {%8,%9}, {%0,%1,%2,%3};" \
    : "+f"((d)[0]), "+f"((d)[1]), "+f"((d)[2]), "+f"((d)[3]) \
    : "r"((a)[0]), "r"((a)[1]), "r"((a)[2]), "r"((a)[3]), "r"(b0), "r"(b1))

// smem byte offsets for attn (K/V have 2 buffers of 64*ROWB each)
#define OQH 0
#define OQL (OQH + BM * ROWB)
#define OKH (OQL + BM * ROWB)
#define OKL (OKH + 2 * BN * ROWB)
#define OVH (OKL + 2 * BN * ROWB)
#define OVL (OVH + 2 * BN * ROWB)
#define SMEM_BYTES (OVL + 2 * BN * ROWB)   // 110592

// ---------------------------------------------------------------------------
// Flash attention, FA2-style mma.sync bf16 hi/lo split. (unchanged from R9)
// ---------------------------------------------------------------------------
__global__ __launch_bounds__(256, 1) void attn_kernel() {
    extern __shared__ char dynsm[];
    const int tid = threadIdx.x, lane = tid & 31, wid = tid >> 5;
    const int qbase = blockIdx.x * BM;
    const int kbase = blockIdx.y * KVPER;
    const uint32_t sb = smem_u32(dynsm);

#pragma unroll
    for (int i = 0; i < 4; i++) {
        int c = tid + i * 256;
        uint32_t d = (uint32_t)((c >> 3) * ROWB + (c & 7) * 16);
        size_t sByte = ((size_t)(qbase + (c >> 3)) * DIM) * 2 + (c & 7) * 16;
        cpa16(sb + OQH + d, (const char*)g_Qh + sByte);
        cpa16(sb + OQL + d, (const char*)g_Ql + sByte);
    }
#pragma unroll
    for (int i = 0; i < 2; i++) {
        int c = tid + i * 256;
        uint32_t d = (uint32_t)((c >> 3) * ROWB + (c & 7) * 16);
        size_t sByte = ((size_t)(kbase + (c >> 3)) * DIM) * 2 + (c & 7) * 16;
        cpa16(sb + OKH + d, (const char*)g_Kh + sByte);
        cpa16(sb + OKL + d, (const char*)g_Kl + sByte);
        cpa16(sb + OVH + d, (const char*)g_Vh + sByte);
        cpa16(sb + OVL + d, (const char*)g_Vl + sByte);
    }
    CP_COMMIT(); CP_WAIT0();
    __syncthreads();

    uint32_t qh[4][4], ql[4][4];
    {
        uint32_t r = (uint32_t)(wid * 16 + (lane & 15));
        uint32_t bo = ((lane >> 4) & 1) << 4;
#pragma unroll
        for (int c = 0; c < 4; c++) {
            LDSM4(qh[c], sb + OQH + r * ROWB + c * 32 + bo);
            LDSM4(ql[c], sb + OQL + r * ROWB + c * 32 + bo);
        }
    }

    float o[8][4];
#pragma unroll
    for (int j = 0; j < 8; j++)
#pragma unroll
        for (int k = 0; k < 4; k++) o[j][k] = 0.f;
    float m0 = -1e30f, m1 = -1e30f, l0 = 0.f, l1 = 0.f;

    const int krow = (lane & 7) + ((lane & 16) ? 8 : 0);
    const int kbyt = (lane & 8) ? 16 : 0;
    const int vrow = (lane & 7) + ((lane & 8) ? 8 : 0);
    const int vbyt = (lane & 16) ? 16 : 0;

    for (int t = 0; t < NT; t++) {
        const int buf = t & 1, nb = buf ^ 1;
        if (t + 1 < NT) {
            int kr = kbase + (t + 1) * BN;
#pragma unroll
            for (int i = 0; i < 2; i++) {
                int c = tid + i * 256;
                uint32_t d = (uint32_t)(nb * BN * ROWB + (c >> 3) * ROWB + (c & 7) * 16);
                size_t sByte = ((size_t)(kr + (c >> 3)) * DIM) * 2 + (c & 7) * 16;
                cpa16(sb + OKH + d, (const char*)g_Kh + sByte);
                cpa16(sb + OKL + d, (const char*)g_Kl + sByte);
                cpa16(sb + OVH + d, (const char*)g_Vh + sByte);
                cpa16(sb + OVL + d, (const char*)g_Vl + sByte);
            }
            CP_COMMIT();
        }

        float s[8][4];
#pragma unroll
        for (int j = 0; j < 8; j++)
#pragma unroll
            for (int k = 0; k < 4; k++) s[j][k] = 0.f;
        const uint32_t kbH = sb + OKH + buf * BN * ROWB;
        const uint32_t kbL = sb + OKL + buf * BN * ROWB;
#pragma unroll
        for (int c = 0; c < 4; c++) {
#pragma unroll
            for (int p = 0; p < 4; p++) {
                uint32_t b[4], bl[4];
                uint32_t ra = (uint32_t)((p * 16 + krow) * ROWB + c * 32 + kbyt);
                LDSM4(b, kbH + ra);
                LDSM4(bl, kbL + ra);
                MMA(s[2 * p],     qh[c], b[0], b[1]);
                MMA(s[2 * p + 1], qh[c], b[2], b[3]);
                MMA(s[2 * p],     ql[c], b[0], b[1]);
                MMA(s[2 * p + 1], ql[c], b[2], b[3]);
                MMA(s[2 * p],     qh[c], bl[0], bl[1]);
                MMA(s[2 * p + 1], qh[c], bl[2], bl[3]);
            }
        }

        float mx0 = -1e30f, mx1 = -1e30f;
#pragma unroll
        for (int j = 0; j < 8; j++) {
            mx0 = fmaxf(mx0, fmaxf(s[j][0], s[j][1]));
            mx1 = fmaxf(mx1, fmaxf(s[j][2], s[j][3]));
        }
        mx0 = fmaxf(mx0, __shfl_xor_sync(0xffffffffu, mx0, 1));
        mx0 = fmaxf(mx0, __shfl_xor_sync(0xffffffffu, mx0, 2));
        mx1 = fmaxf(mx1, __shfl_xor_sync(0xffffffffu, mx1, 1));
        mx1 = fmaxf(mx1, __shfl_xor_sync(0xffffffffu, mx1, 2));
        const float M0 = fmaxf(m0, mx0), M1 = fmaxf(m1, mx1);
        const float c0 = ex2f((m0 - M0) * L2E), c1 = ex2f((m1 - M1) * L2E);
        const float z0 = M0 * L2E, z1 = M1 * L2E;
        m0 = M0; m1 = M1;

        float rs0 = 0.f, rs1 = 0.f;
        uint32_t pah[4][4], pal[4][4];
#pragma unroll
        for (int c = 0; c < 4; c++) {
            float p00 = ex2f(fmaf(s[2 * c][0], L2E, -z0));
            float p01 = ex2f(fmaf(s[2 * c][1], L2E, -z0));
            float p02 = ex2f(fmaf(s[2 * c][2], L2E, -z1));
            float p03 = ex2f(fmaf(s[2 * c][3], L2E, -z1));
            float p10 = ex2f(fmaf(s[2 * c + 1][0], L2E, -z0));
            float p11 = ex2f(fmaf(s[2 * c + 1][1], L2E, -z0));
            float p12 = ex2f(fmaf(s[2 * c + 1][2], L2E, -z1));
            float p13 = ex2f(fmaf(s[2 * c + 1][3], L2E, -z1));
            rs0 += p00 + p01 + p10 + p11;
            rs1 += p02 + p03 + p12 + p13;
            pah[c][0] = packbf(p00, p01);
            pah[c][1] = packbf(p02, p03);
            pah[c][2] = packbf(p10, p11);
            pah[c][3] = packbf(p12, p13);
#pragma unroll
            for (int k = 0; k < 4; k++) {
                float hl = __uint_as_float(pah[c][k] << 16);
                float hh = __uint_as_float(pah[c][k] & 0xFFFF0000u);
                float e0 = (k == 0 ? p00 : k == 1 ? p02 : k == 2 ? p10 : p12) - hl;
                float e1 = (k == 0 ? p01 : k == 1 ? p03 : k == 2 ? p11 : p13) - hh;
                pal[c][k] = packbf(e0, e1);
            }
        }
        rs0 += __shfl_xor_sync(0xffffffffu, rs0, 1);
        rs0 += __shfl_xor_sync(0xffffffffu, rs0, 2);
        rs1 += __shfl_xor_sync(0xffffffffu, rs1, 1);
        rs1 += __shfl_xor_sync(0xffffffffu, rs1, 2);
        l0 = l0 * c0 + rs0;
        l1 = l1 * c1 + rs1;
#pragma unroll
        for (int j = 0; j < 8; j++) {
            o[j][0] *= c0; o[j][1] *= c0;
            o[j][2] *= c1; o[j][3] *= c1;
        }

        const uint32_t vbH = sb + OVH + buf * BN * ROWB;
        const uint32_t vbL = sb + OVL + buf * BN * ROWB;
#pragma unroll
        for (int c = 0; c < 4; c++) {
#pragma unroll
            for (int p = 0; p < 4; p++) {
                uint32_t b[4], bl[4];
                uint32_t ra = (uint32_t)((c * 16 + vrow) * ROWB + p * 32 + vbyt);
                LDSM4T(b, vbH + ra);
                LDSM4T(bl, vbL + ra);
                MMA(o[2 * p],     pah[c], b[0], b[1]);
                MMA(o[2 * p + 1], pah[c], b[2], b[3]);
                MMA(o[2 * p],     pal[c], b[0], b[1]);
                MMA(o[2 * p + 1], pal[c], b[2], b[3]);
                MMA(o[2 * p],     pah[c], bl[0], bl[1]);
                MMA(o[2 * p + 1], pah[c], bl[2], bl[3]);
            }
        }
        if (t + 1 < NT) { CP_WAIT0(); __syncthreads(); }
    }

    const int r0 = qbase + wid * 16 + (lane >> 2);
    const int r1 = r0 + 8;
    const int col = (lane & 3) * 2;
    size_t b0 = ((size_t)blockIdx.y * SEQ + r0) * DIM;
    size_t b1 = ((size_t)blockIdx.y * SEQ + r1) * DIM;
#pragma unroll
    for (int j = 0; j < 8; j++) {
        *(float2*)&g_Op[b0 + j * 8 + col] = make_float2(o[j][0], o[j][1]);
        *(float2*)&g_Op[b1 + j * 8 + col] = make_float2(o[j][2], o[j][3]);
    }
    if ((lane & 3) == 0) {
        g_m[blockIdx.y * SEQ + r0] = m0;
        g_m[blockIdx.y * SEQ + r1] = m1;
        g_l[blockIdx.y * SEQ + r0] = l0;
        g_l[blockIdx.y * SEQ + r1] = l1;
    }
}

// -------- merge the 2 KV-split partials (unchanged) --------
__global__ __launch_bounds__(256, 1) void merge_kernel(float* __restrict__ out) {
    int e = (blockIdx.x * 256 + threadIdx.x) * 4;
    int s = e / DIM;
    float m0 = g_m[s], m1 = g_m[SEQ + s];
    float M = fmaxf(m0, m1);
    float w0 = ex2f((m0 - M) * L2E), w1 = ex2f((m1 - M) * L2E);
    float inv = 1.f / (w0 * g_l[s] + w1 * g_l[SEQ + s]);
    float4 a = *(const float4*)&g_Op[e];
    float4 b = *(const float4*)&g_Op[SEQ * DIM + e];
    float4 r;
    r.x = (w0 * a.x + w1 * b.x) * inv;
    r.y = (w0 * a.y + w1 * b.y) * inv;
    r.z = (w0 * a.z + w1 * b.z) * inv;
    r.w = (w0 * a.w + w1 * b.w) * inv;
    *(float4*)&out[e] = r;
}

// ---------------------------------------------------------------------------
// QKV projection, 3-term tf32 split, v4 = v3 + FIX:
// R13 (rel_err 0.43) removed the trailing stage barrier; the next stage's
// cp.async prefetch (issued BEFORE the first barrier of that stage) then
// overwrote the buffer lagging warps were still reading in their MMA loop.
// Restore the end-of-stage __syncthreads() (R12 had it).
// ---------------------------------------------------------------------------
#define QBM 128
#define QBK 32
#define NSTG (EMB / QBK)   // 24
#define XRB 36             // floats per X smem row (32 data + 4 pad)
#define WRB 72             // elems per W smem row (64 data + 8 pad)
#define QSM_XF 0                         // f32 [2][QBM*XRB]
#define QSM_WF (2 * QBM * XRB)           // f32 [2][QBK*WRB]
#define QSM_WH (QSM_WF + 2 * QBK * WRB)  // u32 [QBK*WRB]
#define QSM_WL (QSM_WH + QBK * WRB)      // u32 [QBK*WRB]
#define QSMEM ((QSM_WL + QBK * WRB) * 4) // 73728 B

__global__ __launch_bounds__(256, 2) void qkv_kernel(
    const float* __restrict__ X, const float* __restrict__ WQ,
    const float* __restrict__ WK, const float* __restrict__ WV)
{
    extern __shared__ float qsm[];
    float* Xf = qsm + QSM_XF;
    float* Wf = qsm + QSM_WF;
    uint32_t* Whi = (uint32_t*)(qsm + QSM_WH);
    uint32_t* Wlo = (uint32_t*)(qsm + QSM_WL);

    const int tid = threadIdx.x, lane = tid & 31, wid = tid >> 5;
    const int mbase = blockIdx.x * QBM;
    const int w = blockIdx.y;
    const float* __restrict__ W = (w == 0) ? WQ : ((w == 1) ? WK : WV);
    const uint32_t xs_u = smem_u32(Xf);
    const uint32_t ws_u = smem_u32(Wf);

    auto loadstage = [&](int buf, int kb) {
        uint32_t xd = xs_u + (uint32_t)(buf * QBM * XRB * 4);
#pragma unroll
        for (int i = 0; i < 4; i++) {
            int id = tid + i * 256;          // 0..1023 (1024 float4)
            int r = id >> 3, c = (id & 7) * 4;
            cpa16(xd + (uint32_t)(r * (XRB * 4) + c * 4),
                  X + (size_t)(mbase + r) * EMB + kb + c);
        }
        uint32_t wd = ws_u + (uint32_t)(buf * QBK * WRB * 4);
#pragma unroll
        for (int i = 0; i < 2; i++) {
            int id = tid + i * 256;          // 0..511 (512 float4)
            int r = id >> 4, c = (id & 15) * 4;
            cpa16(wd + (uint32_t)(r * (WRB * 4) + c * 4),
                  W + (size_t)(kb + r) * DIM + c);
        }
    };

    float acc[8][4];
#pragma unroll
    for (int nt = 0; nt < 8; nt++)
#pragma unroll
        for (int k = 0; k < 4; k++) acc[nt][k] = 0.f;

    const int a_r = wid * 16 + (lane >> 2);   // A-frag base row (warp owns 16)
    const int a_c = lane & 3;
    const int b_n = lane >> 2;

    loadstage(0, 0);
    CP_COMMIT();

    for (int s = 0; s < NSTG; s++) {
        const int buf = s & 1;
        const bool pre = (s + 1 < NSTG);
        if (pre) { loadstage(buf ^ 1, (s + 1) * QBK); CP_COMMIT(); }
        if (pre) CP_WAIT1(); else CP_WAIT0();
        __syncthreads();   // stage-s tiles resident; prior MMA done with Whi/Wlo

        // prepass: split W tile into tf32 hi/lo (2048 elems, 8 per thread)
        const float* wf = Wf + buf * QBK * WRB;
#pragma unroll
        for (int i = 0; i < 8; i++) {
            int id = tid + i * 256;          // 0..2047
            int addr = (id >> 6) * WRB + (id & 63);
            float v = wf[addr];
            uint32_t h = totf(v);
            Whi[addr] = h;
            Wlo[addr] = totf(v - __uint_as_float(h));
        }
        __syncthreads();

        const float* xb = Xf + buf * QBM * XRB;
#pragma unroll
        for (int j = 0; j < 4; j++) {
            int cc = a_c + j * 8;
            float v0 = xb[a_r * XRB + cc];
            float v1 = xb[(a_r + 8) * XRB + cc];
            float v2 = xb[a_r * XRB + cc + 4];
            float v3 = xb[(a_r + 8) * XRB + cc + 4];
            uint32_t uah[4], ual[4];
            uah[0] = totf(v0); ual[0] = totf(v0 - __uint_as_float(uah[0]));
            uah[1] = totf(v1); ual[1] = totf(v1 - __uint_as_float(uah[1]));
            uah[2] = totf(v2); ual[2] = totf(v2 - __uint_as_float(uah[2]));
            uah[3] = totf(v3); ual[3] = totf(v3 - __uint_as_float(uah[3]));
            const int k0 = j * 8 + a_c;
#pragma unroll
            for (int nt = 0; nt < 8; nt++) {
                int n = nt * 8 + b_n;
                uint32_t bh0 = Whi[k0 * WRB + n];
                uint32_t bh1 = Whi[(k0 + 4) * WRB + n];
                uint32_t bl0 = Wlo[k0 * WRB + n];
                uint32_t bl1 = Wlo[(k0 + 4) * WRB + n];
                MMAT(acc[nt], uah, bh0, bh1);
                MMAT(acc[nt], ual, bh0, bh1);
                MMAT(acc[nt], uah, bl0, bl1);
            }
        }
        // FIX (R13 race): no thread may start the next stage's prefetch
        // (which overwrites buffer buf^1^1 = buf) until ALL threads are done
        // reading this stage's Xf/Wf tiles.
        __syncthreads();
    }

    // epilogue: scale (Q only) + bf16 hi/lo split + store
    const float scale = (w == 0) ? 0.125f : 1.0f;
    __nv_bfloat16* dh = (w == 0) ? g_Qh : ((w == 1) ? g_Kh : g_Vh);
    __nv_bfloat16* dl = (w == 0) ? g_Ql : ((w == 1) ? g_Kl : g_Vl);
    const int r0 = mbase + wid * 16 + (lane >> 2);
#pragma unroll
    for (int nt = 0; nt < 8; nt++) {
        int col = nt * 8 + (lane & 3) * 2;
        float v0 = acc[nt][0] * scale, v1 = acc[nt][1] * scale;
        uint32_t h = packbf(v0, v1);
        uint32_t lo = packbf(v0 - __uint_as_float(h << 16),
                             v1 - __uint_as_float(h & 0xFFFF0000u));
        *(uint32_t*)&dh[(size_t)r0 * DIM + col] = h;
        *(uint32_t*)&dl[(size_t)r0 * DIM + col] = lo;
        float v2 = acc[nt][2] * scale, v3 = acc[nt][3] * scale;
        h = packbf(v2, v3);
        lo = packbf(v2 - __uint_as_float(h << 16),
                    v3 - __uint_as_float(h & 0xFFFF0000u));
        *(uint32_t*)&dh[(size_t)(r0 + 8) * DIM + col] = h;
        *(uint32_t*)&dl[(size_t)(r0 + 8) * DIM + col] = lo;
    }
}

extern "C" void kernel_launch(void* const* d_in, const int* in_sizes, int n_in,
                              void* d_out, int out_size)
{
    const float* X  = (const float*)d_in[0];
    const float* WQ = (const float*)d_in[1];
    const float* WK = (const float*)d_in[2];
    const float* WV = (const float*)d_in[3];
    float* out = (float*)d_out;

    cudaFuncSetAttribute(attn_kernel,
                         cudaFuncAttributeMaxDynamicSharedMemorySize, SMEM_BYTES);
    cudaFuncSetAttribute(qkv_kernel,
                         cudaFuncAttributeMaxDynamicSharedMemorySize, QSMEM);

    dim3 g1(SEQ / QBM, 3);
    qkv_kernel<<<g1, 256, QSMEM>>>(X, WQ, WK, WV);
    dim3 ga(SEQ / BM, NSPLIT);
    attn_kernel<<<ga, 256, SMEM_BYTES>>>();
    merge_kernel<<<SEQ * DIM / 1024, 256>>>(out);
}

// round 17
// speedup vs baseline: 1.0088x; 1.0088x over previous
#include <cuda_runtime.h>
#include <cuda_bf16.h>
#include <cstdint>

#define SEQ 8192
#define EMB 768
#define DIM 64
#define BM 128
#define BN 64
#define NSPLIT 4
#define KVPER (SEQ / NSPLIT)
#define NT (KVPER / BN)
#define L2E 1.4426950408889634f
#define ROWB 144   // padded smem row bytes (64 bf16 = 128B data + 16B pad)

__device__ __nv_bfloat16 g_Qh[SEQ * DIM], g_Ql[SEQ * DIM];
__device__ __nv_bfloat16 g_Kh[SEQ * DIM], g_Kl[SEQ * DIM];
__device__ __nv_bfloat16 g_Vh[SEQ * DIM], g_Vl[SEQ * DIM];
__device__ float g_Op[NSPLIT * SEQ * DIM];
__device__ float g_m[NSPLIT * SEQ], g_l[NSPLIT * SEQ];

__device__ __forceinline__ uint32_t smem_u32(const void* p) {
    uint32_t a;
    asm("{ .reg .u64 t; cvta.to.shared.u64 t, %1; cvt.u32.u64 %0, t; }" : "=r"(a) : "l"(p));
    return a;
}
__device__ __forceinline__ float ex2f(float x) {
    float y; asm("ex2.approx.ftz.f32 %0, %1;" : "=f"(y) : "f"(x)); return y;
}
__device__ __forceinline__ void cpa16(uint32_t dst, const void* src) {
    asm volatile("cp.async.cg.shared.global [%0], [%1], 16;" :: "r"(dst), "l"(src));
}
#define CP_COMMIT() asm volatile("cp.async.commit_group;" ::: "memory")
#define CP_WAIT0()  asm volatile("cp.async.wait_group 0;" ::: "memory")
#define CP_WAIT1()  asm volatile("cp.async.wait_group 1;" ::: "memory")

__device__ __forceinline__ uint32_t packbf(float lo, float hi) {
    uint32_t r; asm("cvt.rn.bf16x2.f32 %0, %1, %2;" : "=r"(r) : "f"(hi), "f"(lo)); return r;
}
__device__ __forceinline__ uint32_t totf(float x) {
    uint32_t r; asm("cvt.rna.tf32.f32 %0, %1;" : "=r"(r) : "f"(x)); return r;
}

#define LDSM4(r, a) asm volatile( \
    "ldmatrix.sync.aligned.m8n8.x4.shared.b16 {%0,%1,%2,%3}, [%4];" \
    : "=r"((r)[0]), "=r"((r)[1]), "=r"((r)[2]), "=r"((r)[3]) : "r"(a))
#define LDSM4T(r, a) asm volatile( \
    "ldmatrix.sync.aligned.m8n8.x4.trans.shared.b16 {%0,%1,%2,%3}, [%4];" \
    : "=r"((r)[0]), "=r"((r)[1]), "=r"((r)[2]), "=r"((r)[3]) : "r"(a))
#define MMA(d, a, b0, b1) asm volatile( \
    "mma.sync.aligned.m16n8k16.row.col.f32.bf16.bf16.f32 " \
    "{%0,%1,%2,%3}, {%4,%5,%6,%7}, {%8,%9}, {%0,%1,%2,%3};" \
    : "+f"((d)[0]), "+f"((d)[1]), "+f"((d)[2]), "+f"((d)[3]) \
    : "r"((a)[0]), "r"((a)[1]), "r"((a)[2]), "r"((a)[3]), "r"(b0), "r"(b1))
#define MMAT(d, a, b0, b1) asm volatile( \
    "mma.sync.aligned.m16n8k8.row.col.f32.tf32.tf32.f32 " \
    "{%0,%1,%2,%3}, {%4,%5,%6,%7}, {%8,%9}, {%0,%1,%2,%3};" \
    : "+f"((d)[0]), "+f"((d)[1]), "+f"((d)[2]), "+f"((d)[3]) \
    : "r"((a)[0]), "r"((a)[1]), "r"((a)[2]), "r"((a)[3]), "r"(b0), "r"(b1))

// smem byte offsets for attn (K/V have 2 buffers of 64*ROWB each)
#define OQH 0
#define OQL (OQH + BM * ROWB)
#define OKH (OQL + BM * ROWB)
#define OKL (OKH + 2 * BN * ROWB)
#define OVH (OKL + 2 * BN * ROWB)
#define OVL (OVH + 2 * BN * ROWB)
#define SMEM_BYTES (OVL + 2 * BN * ROWB)   // 110592 (x2 = 221184 <= 228KB/SM)

// ---------------------------------------------------------------------------
// Flash attention, FA2-style mma.sync bf16 hi/lo split.
// R16/R17: NSPLIT 2->4 (grid 256 CTAs, no idle SMs) + launch_bounds(256,2)
// so 2 CTAs co-reside per SM (smem 2x110592 fits) and one CTA's softmax
// overlaps the other's MMAs. Inner loop identical to R9/R12.
// ---------------------------------------------------------------------------
__global__ __launch_bounds__(256, 2) void attn_kernel() {
    extern __shared__ char dynsm[];
    const int tid = threadIdx.x, lane = tid & 31, wid = tid >> 5;
    const int qbase = blockIdx.x * BM;
    const int kbase = blockIdx.y * KVPER;
    const uint32_t sb = smem_u32(dynsm);

#pragma unroll
    for (int i = 0; i < 4; i++) {
        int c = tid + i * 256;
        uint32_t d = (uint32_t)((c >> 3) * ROWB + (c & 7) * 16);
        size_t sByte = ((size_t)(qbase + (c >> 3)) * DIM) * 2 + (c & 7) * 16;
        cpa16(sb + OQH + d, (const char*)g_Qh + sByte);
        cpa16(sb + OQL + d, (const char*)g_Ql + sByte);
    }
#pragma unroll
    for (int i = 0; i < 2; i++) {
        int c = tid + i * 256;
        uint32_t d = (uint32_t)((c >> 3) * ROWB + (c & 7) * 16);
        size_t sByte = ((size_t)(kbase + (c >> 3)) * DIM) * 2 + (c & 7) * 16;
        cpa16(sb + OKH + d, (const char*)g_Kh + sByte);
        cpa16(sb + OKL + d, (const char*)g_Kl + sByte);
        cpa16(sb + OVH + d, (const char*)g_Vh + sByte);
        cpa16(sb + OVL + d, (const char*)g_Vl + sByte);
    }
    CP_COMMIT(); CP_WAIT0();
    __syncthreads();

    uint32_t qh[4][4], ql[4][4];
    {
        uint32_t r = (uint32_t)(wid * 16 + (lane & 15));
        uint32_t bo = ((lane >> 4) & 1) << 4;
#pragma unroll
        for (int c = 0; c < 4; c++) {
            LDSM4(qh[c], sb + OQH + r * ROWB + c * 32 + bo);
            LDSM4(ql[c], sb + OQL + r * ROWB + c * 32 + bo);
        }
    }

    float o[8][4];
#pragma unroll
    for (int j = 0; j < 8; j++)
#pragma unroll
        for (int k = 0; k < 4; k++) o[j][k] = 0.f;
    float m0 = -1e30f, m1 = -1e30f, l0 = 0.f, l1 = 0.f;

    const int krow = (lane & 7) + ((lane & 16) ? 8 : 0);
    const int kbyt = (lane & 8) ? 16 : 0;
    const int vrow = (lane & 7) + ((lane & 8) ? 8 : 0);
    const int vbyt = (lane & 16) ? 16 : 0;

    for (int t = 0; t < NT; t++) {
        const int buf = t & 1, nb = buf ^ 1;
        if (t + 1 < NT) {
            int kr = kbase + (t + 1) * BN;
#pragma unroll
            for (int i = 0; i < 2; i++) {
                int c = tid + i * 256;
                uint32_t d = (uint32_t)(nb * BN * ROWB + (c >> 3) * ROWB + (c & 7) * 16);
                size_t sByte = ((size_t)(kr + (c >> 3)) * DIM) * 2 + (c & 7) * 16;
                cpa16(sb + OKH + d, (const char*)g_Kh + sByte);
                cpa16(sb + OKL + d, (const char*)g_Kl + sByte);
                cpa16(sb + OVH + d, (const char*)g_Vh + sByte);
                cpa16(sb + OVL + d, (const char*)g_Vl + sByte);
            }
            CP_COMMIT();
        }

        float s[8][4];
#pragma unroll
        for (int j = 0; j < 8; j++)
#pragma unroll
            for (int k = 0; k < 4; k++) s[j][k] = 0.f;
        const uint32_t kbH = sb + OKH + buf * BN * ROWB;
        const uint32_t kbL = sb + OKL + buf * BN * ROWB;
#pragma unroll
        for (int c = 0; c < 4; c++) {
#pragma unroll
            for (int p = 0; p < 4; p++) {
                uint32_t b[4], bl[4];
                uint32_t ra = (uint32_t)((p * 16 + krow) * ROWB + c * 32 + kbyt);
                LDSM4(b, kbH + ra);
                LDSM4(bl, kbL + ra);
                MMA(s[2 * p],     qh[c], b[0], b[1]);
                MMA(s[2 * p + 1], qh[c], b[2], b[3]);
                MMA(s[2 * p],     ql[c], b[0], b[1]);
                MMA(s[2 * p + 1], ql[c], b[2], b[3]);
                MMA(s[2 * p],     qh[c], bl[0], bl[1]);
                MMA(s[2 * p + 1], qh[c], bl[2], bl[3]);
            }
        }

        float mx0 = -1e30f, mx1 = -1e30f;
#pragma unroll
        for (int j = 0; j < 8; j++) {
            mx0 = fmaxf(mx0, fmaxf(s[j][0], s[j][1]));
            mx1 = fmaxf(mx1, fmaxf(s[j][2], s[j][3]));
        }
        mx0 = fmaxf(mx0, __shfl_xor_sync(0xffffffffu, mx0, 1));
        mx0 = fmaxf(mx0, __shfl_xor_sync(0xffffffffu, mx0, 2));
        mx1 = fmaxf(mx1, __shfl_xor_sync(0xffffffffu, mx1, 1));
        mx1 = fmaxf(mx1, __shfl_xor_sync(0xffffffffu, mx1, 2));
        const float M0 = fmaxf(m0, mx0), M1 = fmaxf(m1, mx1);
        const float c0 = ex2f((m0 - M0) * L2E), c1 = ex2f((m1 - M1) * L2E);
        const float z0 = M0 * L2E, z1 = M1 * L2E;
        m0 = M0; m1 = M1;

        float rs0 = 0.f, rs1 = 0.f;
        uint32_t pah[4][4], pal[4][4];
#pragma unroll
        for (int c = 0; c < 4; c++) {
            float p00 = ex2f(fmaf(s[2 * c][0], L2E, -z0));
            float p01 = ex2f(fmaf(s[2 * c][1], L2E, -z0));
            float p02 = ex2f(fmaf(s[2 * c][2], L2E, -z1));
            float p03 = ex2f(fmaf(s[2 * c][3], L2E, -z1));
            float p10 = ex2f(fmaf(s[2 * c + 1][0], L2E, -z0));
            float p11 = ex2f(fmaf(s[2 * c + 1][1], L2E, -z0));
            float p12 = ex2f(fmaf(s[2 * c + 1][2], L2E, -z1));
            float p13 = ex2f(fmaf(s[2 * c + 1][3], L2E, -z1));
            rs0 += p00 + p01 + p10 + p11;
            rs1 += p02 + p03 + p12 + p13;
            pah[c][0] = packbf(p00, p01);
            pah[c][1] = packbf(p02, p03);
            pah[c][2] = packbf(p10, p11);
            pah[c][3] = packbf(p12, p13);
#pragma unroll
            for (int k = 0; k < 4; k++) {
                float hl = __uint_as_float(pah[c][k] << 16);
                float hh = __uint_as_float(pah[c][k] & 0xFFFF0000u);
                float e0 = (k == 0 ? p00 : k == 1 ? p02 : k == 2 ? p10 : p12) - hl;
                float e1 = (k == 0 ? p01 : k == 1 ? p03 : k == 2 ? p11 : p13) - hh;
                pal[c][k] = packbf(e0, e1);
            }
        }
        rs0 += __shfl_xor_sync(0xffffffffu, rs0, 1);
        rs0 += __shfl_xor_sync(0xffffffffu, rs0, 2);
        rs1 += __shfl_xor_sync(0xffffffffu, rs1, 1);
        rs1 += __shfl_xor_sync(0xffffffffu, rs1, 2);
        l0 = l0 * c0 + rs0;
        l1 = l1 * c1 + rs1;
#pragma unroll
        for (int j = 0; j < 8; j++) {
            o[j][0] *= c0; o[j][1] *= c0;
            o[j][2] *= c1; o[j][3] *= c1;
        }

        const uint32_t vbH = sb + OVH + buf * BN * ROWB;
        const uint32_t vbL = sb + OVL + buf * BN * ROWB;
#pragma unroll
        for (int c = 0; c < 4; c++) {
#pragma unroll
            for (int p = 0; p < 4; p++) {
                uint32_t b[4], bl[4];
                uint32_t ra = (uint32_t)((c * 16 + vrow) * ROWB + p * 32 + vbyt);
                LDSM4T(b, vbH + ra);
                LDSM4T(bl, vbL + ra);
                MMA(o[2 * p],     pah[c], b[0], b[1]);
                MMA(o[2 * p + 1], pah[c], b[2], b[3]);
                MMA(o[2 * p],     pal[c], b[0], b[1]);
                MMA(o[2 * p + 1], pal[c], b[2], b[3]);
                MMA(o[2 * p],     pah[c], bl[0], bl[1]);
                MMA(o[2 * p + 1], pah[c], bl[2], bl[3]);
            }
        }
        if (t + 1 < NT) { CP_WAIT0(); __syncthreads(); }
    }

    const int r0 = qbase + wid * 16 + (lane >> 2);
    const int r1 = r0 + 8;
    const int col = (lane & 3) * 2;
    size_t b0 = ((size_t)blockIdx.y * SEQ + r0) * DIM;
    size_t b1 = ((size_t)blockIdx.y * SEQ + r1) * DIM;
#pragma unroll
    for (int j = 0; j < 8; j++) {
        *(float2*)&g_Op[b0 + j * 8 + col] = make_float2(o[j][0], o[j][1]);
        *(float2*)&g_Op[b1 + j * 8 + col] = make_float2(o[j][2], o[j][3]);
    }
    if ((lane & 3) == 0) {
        g_m[blockIdx.y * SEQ + r0] = m0;
        g_m[blockIdx.y * SEQ + r1] = m1;
        g_l[blockIdx.y * SEQ + r0] = l0;
        g_l[blockIdx.y * SEQ + r1] = l1;
    }
}

// -------- merge the NSPLIT KV-split partials --------
__global__ __launch_bounds__(256, 1) void merge_kernel(float* __restrict__ out) {
    int e = (blockIdx.x * 256 + threadIdx.x) * 4;
    int s = e / DIM;
    float M = -1e30f;
#pragma unroll
    for (int k = 0; k < NSPLIT; k++) M = fmaxf(M, g_m[k * SEQ + s]);
    float denom = 0.f;
    float wk[NSPLIT];
#pragma unroll
    for (int k = 0; k < NSPLIT; k++) {
        wk[k] = ex2f((g_m[k * SEQ + s] - M) * L2E);
        denom += wk[k] * g_l[k * SEQ + s];
    }
    float inv = 1.f / denom;
    float4 r = make_float4(0.f, 0.f, 0.f, 0.f);
#pragma unroll
    for (int k = 0; k < NSPLIT; k++) {
        float4 a = *(const float4*)&g_Op[(size_t)k * SEQ * DIM + e];
        r.x += wk[k] * a.x; r.y += wk[k] * a.y;
        r.z += wk[k] * a.z; r.w += wk[k] * a.w;
    }
    r.x *= inv; r.y *= inv; r.z *= inv; r.w *= inv;
    *(float4*)&out[e] = r;
}

// ---------------------------------------------------------------------------
// QKV projection: exact R12 version (measured 67us best) — 128 threads,
// inline 3-term tf32 split. Further qkv tuning was measured neutral (R15).
// ---------------------------------------------------------------------------
#define QBM 128
#define QBK 32
#define NSTG (EMB / QBK)   // 24
#define XRB 36             // floats per X smem row (32 data + 4 pad)
#define WRB 72             // floats per W smem row (64 data + 8 pad)
#define QSMEM ((2 * QBM * XRB + 2 * QBK * WRB) * 4)   // 55296 B

__global__ __launch_bounds__(128, 2) void qkv_kernel(
    const float* __restrict__ X, const float* __restrict__ WQ,
    const float* __restrict__ WK, const float* __restrict__ WV)
{
    extern __shared__ float qsm[];
    float* Xs = qsm;                        // [2][QBM*XRB]
    float* Wsm = qsm + 2 * QBM * XRB;       // [2][QBK*WRB]

    const int tid = threadIdx.x, lane = tid & 31, wid = tid >> 5;
    const int mbase = blockIdx.x * QBM;
    const int w = blockIdx.y;
    const float* __restrict__ W = (w == 0) ? WQ : ((w == 1) ? WK : WV);
    const uint32_t xs_u = smem_u32(Xs);
    const uint32_t ws_u = smem_u32(Wsm);

    auto loadstage = [&](int buf, int kb) {
        uint32_t xd = xs_u + (uint32_t)(buf * QBM * XRB * 4);
#pragma unroll
        for (int i = 0; i < 8; i++) {
            int id = tid + i * 128;          // 0..1023
            int r = id >> 3, c = id & 7;
            cpa16(xd + (uint32_t)(r * (XRB * 4) + c * 16),
                  X + (size_t)(mbase + r) * EMB + kb + c * 4);
        }
        uint32_t wd = ws_u + (uint32_t)(buf * QBK * WRB * 4);
#pragma unroll
        for (int i = 0; i < 4; i++) {
            int id = tid + i * 128;          // 0..511
            int r = id >> 4, c = id & 15;
            cpa16(wd + (uint32_t)(r * (WRB * 4) + c * 16),
                  W + (size_t)(kb + r) * DIM + c * 4);
        }
    };

    float acc[2][8][4];
#pragma unroll
    for (int mt = 0; mt < 2; mt++)
#pragma unroll
        for (int nt = 0; nt < 8; nt++)
#pragma unroll
            for (int k = 0; k < 4; k++) acc[mt][nt][k] = 0.f;

    const int a_r = wid * 32 + (lane >> 2);
    const int a_c = lane & 3;
    const int b_n = lane >> 2;

    loadstage(0, 0);
    CP_COMMIT();

    for (int s = 0; s < NSTG; s++) {
        const int buf = s & 1;
        const bool pre = (s + 1 < NSTG);
        if (pre) { loadstage(buf ^ 1, (s + 1) * QBK); CP_COMMIT(); }
        if (pre) CP_WAIT1(); else CP_WAIT0();
        __syncthreads();
        const float* xb = Xs + buf * QBM * XRB;
        const float* wb = Wsm + buf * QBK * WRB;
#pragma unroll
        for (int j = 0; j < 4; j++) {
            uint32_t uah[2][4], ual[2][4], ubh[8][2], ubl[8][2];
#pragma unroll
            for (int mt = 0; mt < 2; mt++) {
                int r0 = a_r + mt * 16;
                int cc = a_c + j * 8;
                float v0 = xb[r0 * XRB + cc];
                float v1 = xb[(r0 + 8) * XRB + cc];
                float v2 = xb[r0 * XRB + cc + 4];
                float v3 = xb[(r0 + 8) * XRB + cc + 4];
                uah[mt][0] = totf(v0); ual[mt][0] = totf(v0 - __uint_as_float(uah[mt][0]));
                uah[mt][1] = totf(v1); ual[mt][1] = totf(v1 - __uint_as_float(uah[mt][1]));
                uah[mt][2] = totf(v2); ual[mt][2] = totf(v2 - __uint_as_float(uah[mt][2]));
                uah[mt][3] = totf(v3); ual[mt][3] = totf(v3 - __uint_as_float(uah[mt][3]));
            }
#pragma unroll
            for (int nt = 0; nt < 8; nt++) {
                int k0 = j * 8 + a_c;
                int n = nt * 8 + b_n;
                float w0 = wb[k0 * WRB + n];
                float w1 = wb[(k0 + 4) * WRB + n];
                ubh[nt][0] = totf(w0); ubl[nt][0] = totf(w0 - __uint_as_float(ubh[nt][0]));
                ubh[nt][1] = totf(w1); ubl[nt][1] = totf(w1 - __uint_as_float(ubh[nt][1]));
            }
#pragma unroll
            for (int mt = 0; mt < 2; mt++)
#pragma unroll
                for (int nt = 0; nt < 8; nt++) {
                    MMAT(acc[mt][nt], uah[mt], ubh[nt][0], ubh[nt][1]);
                    MMAT(acc[mt][nt], ual[mt], ubh[nt][0], ubh[nt][1]);
                    MMAT(acc[mt][nt], uah[mt], ubl[nt][0], ubl[nt][1]);
                }
        }
        __syncthreads();
    }

    // epilogue: scale (Q only) + bf16 hi/lo split + store
    const float scale = (w == 0) ? 0.125f : 1.0f;
    __nv_bfloat16* dh = (w == 0) ? g_Qh : ((w == 1) ? g_Kh : g_Vh);
    __nv_bfloat16* dl = (w == 0) ? g_Ql : ((w == 1) ? g_Kl : g_Vl);
#pragma unroll
    for (int mt = 0; mt < 2; mt++) {
        int r0 = mbase + wid * 32 + mt * 16 + (lane >> 2);
#pragma unroll
        for (int nt = 0; nt < 8; nt++) {
            int col = nt * 8 + (lane & 3) * 2;
            float v0 = acc[mt][nt][0] * scale, v1 = acc[mt][nt][1] * scale;
            uint32_t h = packbf(v0, v1);
            uint32_t lo = packbf(v0 - __uint_as_float(h << 16),
                                 v1 - __uint_as_float(h & 0xFFFF0000u));
            *(uint32_t*)&dh[(size_t)r0 * DIM + col] = h;
            *(uint32_t*)&dl[(size_t)r0 * DIM + col] = lo;
            float v2 = acc[mt][nt][2] * scale, v3 = acc[mt][nt][3] * scale;
            h = packbf(v2, v3);
            lo = packbf(v2 - __uint_as_float(h << 16),
                        v3 - __uint_as_float(h & 0xFFFF0000u));
            *(uint32_t*)&dh[(size_t)(r0 + 8) * DIM + col] = h;
            *(uint32_t*)&dl[(size_t)(r0 + 8) * DIM + col] = lo;
        }
    }
}

extern "C" void kernel_launch(void* const* d_in, const int* in_sizes, int n_in,
                              void* d_out, int out_size)
{
    const float* X  = (const float*)d_in[0];
    const float* WQ = (const float*)d_in[1];
    const float* WK = (const float*)d_in[2];
    const float* WV = (const float*)d_in[3];
    float* out = (float*)d_out;

    cudaFuncSetAttribute(attn_kernel,
                         cudaFuncAttributeMaxDynamicSharedMemorySize, SMEM_BYTES);
    cudaFuncSetAttribute(qkv_kernel,
                         cudaFuncAttributeMaxDynamicSharedMemorySize, QSMEM);

    dim3 g1(SEQ / QBM, 3);
    qkv_kernel<<<g1, 128, QSMEM>>>(X, WQ, WK, WV);
    dim3 ga(SEQ / BM, NSPLIT);
    attn_kernel<<<ga, 256, SMEM_BYTES>>>();
    merge_kernel<<<SEQ * DIM / 1024, 256>>>(out);
}